// round 1
// baseline (speedup 1.0000x reference)
#include <cuda_runtime.h>
#include <cstdint>

// Dice over B=4 batches, C=5 classes, N = 64*256*256 = 4,194,304 voxels/batch.
// Inputs: predicted [B,D,H,W] int32, target [B,D,H,W] int32.
// Output: 5 float32 (per-class dice averaged over batch).

#define NUM_CLASSES 5
#define BATCHES     4
#define N_PER_BATCH (64 * 256 * 256)          // 4,194,304 elements
#define INT4_PER_BATCH (N_PER_BATCH / 4)      // 1,048,576 int4
#define THREADS     256
#define BLOCKS_X    512                        // 512*256 = 131072 threads/batch
#define ITERS       (INT4_PER_BATCH / (BLOCKS_X * THREADS))  // exactly 8

// Scratch: per batch 15 counters: pred[5], tar[5], inter[5]
__device__ unsigned int g_counts[BATCHES * 15];

__global__ void zero_counts_kernel() {
    if (threadIdx.x < BATCHES * 15) g_counts[threadIdx.x] = 0u;
}

__global__ __launch_bounds__(THREADS) void count_kernel(
    const int4* __restrict__ pred, const int4* __restrict__ tar)
{
    const unsigned batch = blockIdx.y;
    const unsigned base  = batch * (unsigned)INT4_PER_BATCH;
    const unsigned idx   = blockIdx.x * THREADS + threadIdx.x;  // 0..131071

    unsigned cnt[15];
#pragma unroll
    for (int k = 0; k < 15; ++k) cnt[k] = 0u;

#pragma unroll
    for (int it = 0; it < ITERS; ++it) {
        const unsigned off = base + idx + (unsigned)it * (BLOCKS_X * THREADS);
        int4 p = pred[off];
        int4 t = tar[off];
        int pe[4] = {p.x, p.y, p.z, p.w};
        int te[4] = {t.x, t.y, t.z, t.w};
#pragma unroll
        for (int e = 0; e < 4; ++e) {
#pragma unroll
            for (int c = 0; c < NUM_CLASSES; ++c) {
                unsigned bp = __ballot_sync(0xFFFFFFFFu, pe[e] == c);
                unsigned bt = __ballot_sync(0xFFFFFFFFu, te[e] == c);
                cnt[c]      += (unsigned)__popc(bp);
                cnt[5 + c]  += (unsigned)__popc(bt);
                cnt[10 + c] += (unsigned)__popc(bp & bt);
            }
        }
    }

    // Counters are warp-uniform (ballot/popc identical across lanes).
    // Lane 0 of each warp deposits into smem; then 15 threads atomicAdd.
    __shared__ unsigned s[THREADS / 32][15];
    const unsigned warp = threadIdx.x >> 5;
    if ((threadIdx.x & 31u) == 0u) {
#pragma unroll
        for (int k = 0; k < 15; ++k) s[warp][k] = cnt[k];
    }
    __syncthreads();
    if (threadIdx.x < 15) {
        unsigned tot = 0u;
#pragma unroll
        for (int w = 0; w < THREADS / 32; ++w) tot += s[w][threadIdx.x];
        atomicAdd(&g_counts[batch * 15 + threadIdx.x], tot);
    }
}

__global__ void dice_kernel(float* __restrict__ out) {
    const int c = threadIdx.x;
    if (c < NUM_CLASSES) {
        float acc = 0.0f;
#pragma unroll
        for (int b = 0; b < BATCHES; ++b) {
            float ps = (float)g_counts[b * 15 + c];
            float ts = (float)g_counts[b * 15 + 5 + c];
            float is = (float)g_counts[b * 15 + 10 + c];
            float den = ps + ts;
            float num = 2.0f * is;
            if (den == 0.0f) { num = 1.0f; den = 1.0f; }
            acc += num / den;
        }
        out[c] = acc * (1.0f / (float)BATCHES);
    }
}

extern "C" void kernel_launch(void* const* d_in, const int* in_sizes, int n_in,
                              void* d_out, int out_size) {
    const int4* pred = (const int4*)d_in[0];
    const int4* tar  = (const int4*)d_in[1];
    float* out = (float*)d_out;

    zero_counts_kernel<<<1, 64>>>();
    dim3 grid(BLOCKS_X, BATCHES);
    count_kernel<<<grid, THREADS>>>(pred, tar);
    dice_kernel<<<1, 32>>>(out);
}

// round 2
// speedup vs baseline: 2.2261x; 2.2261x over previous
#include <cuda_runtime.h>
#include <cstdint>

// Dice over B=4 batches, C=5 classes, N = 64*256*256 = 4,194,304 voxels/batch.
// Inputs: predicted [B,D,H,W] int32, target [B,D,H,W] int32.
// Output: 5 float32 (per-class dice averaged over batch).
//
// Strategy: lane-parallel packed histograms. Each thread accumulates its 32
// elements into three 64-bit registers with five 12-bit fields (one per class):
//   acc_p: one-hot(pred) counts, acc_t: one-hot(target), acc_i: pred==target.
// Max field after full warp reduce = 32 lanes * 32 elems = 1024 < 4096: safe.

#define NUM_CLASSES 5
#define BATCHES     4
#define N_PER_BATCH (64 * 256 * 256)          // 4,194,304 elements
#define INT4_PER_BATCH (N_PER_BATCH / 4)      // 1,048,576 int4
#define THREADS     256
#define BLOCKS_X    512                        // 512*256 = 131072 threads/batch
#define ITERS       (INT4_PER_BATCH / (BLOCKS_X * THREADS))  // exactly 8

// Scratch: per batch 15 counters: pred[5], tar[5], inter[5].
// Zero at program load; dice_kernel re-zeroes after reading, so every graph
// replay sees zeros (deterministic).
__device__ unsigned int g_counts[BATCHES * 15];

__global__ __launch_bounds__(THREADS) void count_kernel(
    const int4* __restrict__ pred, const int4* __restrict__ tar)
{
    const unsigned batch = blockIdx.y;
    const unsigned base  = batch * (unsigned)INT4_PER_BATCH;
    const unsigned idx   = blockIdx.x * THREADS + threadIdx.x;  // 0..131071

    unsigned long long acc_p = 0ull, acc_t = 0ull, acc_i = 0ull;

#pragma unroll
    for (int it = 0; it < ITERS; ++it) {
        const unsigned off = base + idx + (unsigned)it * (BLOCKS_X * THREADS);
        int4 p = pred[off];
        int4 t = tar[off];
        int pe[4] = {p.x, p.y, p.z, p.w};
        int te[4] = {t.x, t.y, t.z, t.w};
#pragma unroll
        for (int e = 0; e < 4; ++e) {
            unsigned sp = (unsigned)pe[e] * 12u;
            unsigned st = (unsigned)te[e] * 12u;
            unsigned long long op = 1ull << sp;
            acc_p += op;
            acc_t += 1ull << st;
            if (pe[e] == te[e]) acc_i += op;
        }
    }

    // Warp reduce the packed accumulators (fields can't overflow: <=1024).
#pragma unroll
    for (int o = 16; o > 0; o >>= 1) {
        acc_p += __shfl_down_sync(0xFFFFFFFFu, acc_p, o);
        acc_t += __shfl_down_sync(0xFFFFFFFFu, acc_t, o);
        acc_i += __shfl_down_sync(0xFFFFFFFFu, acc_i, o);
    }

    // Block reduce via smem, then 15 global atomics per block.
    __shared__ unsigned s[15];
    if (threadIdx.x < 15) s[threadIdx.x] = 0u;
    __syncthreads();
    if ((threadIdx.x & 31u) == 0u) {
#pragma unroll
        for (int c = 0; c < NUM_CLASSES; ++c) {
            atomicAdd(&s[c],      (unsigned)((acc_p >> (12 * c)) & 0xFFFull));
            atomicAdd(&s[5 + c],  (unsigned)((acc_t >> (12 * c)) & 0xFFFull));
            atomicAdd(&s[10 + c], (unsigned)((acc_i >> (12 * c)) & 0xFFFull));
        }
    }
    __syncthreads();
    if (threadIdx.x < 15) {
        atomicAdd(&g_counts[batch * 15 + threadIdx.x], s[threadIdx.x]);
    }
}

__global__ void dice_kernel(float* __restrict__ out) {
    const int tid = threadIdx.x;
    float acc = 0.0f;
    if (tid < NUM_CLASSES) {
#pragma unroll
        for (int b = 0; b < BATCHES; ++b) {
            float ps = (float)g_counts[b * 15 + tid];
            float ts = (float)g_counts[b * 15 + 5 + tid];
            float is = (float)g_counts[b * 15 + 10 + tid];
            float den = ps + ts;
            float num = 2.0f * is;
            if (den == 0.0f) { num = 1.0f; den = 1.0f; }
            acc += num / den;
        }
    }
    __syncthreads();  // all reads of g_counts complete before re-zeroing
    if (tid < BATCHES * 15) g_counts[tid] = 0u;
    if (tid < NUM_CLASSES) out[tid] = acc * (1.0f / (float)BATCHES);
}

extern "C" void kernel_launch(void* const* d_in, const int* in_sizes, int n_in,
                              void* d_out, int out_size) {
    const int4* pred = (const int4*)d_in[0];
    const int4* tar  = (const int4*)d_in[1];
    float* out = (float*)d_out;

    dim3 grid(BLOCKS_X, BATCHES);
    count_kernel<<<grid, THREADS>>>(pred, tar);
    dice_kernel<<<1, 64>>>(out);
}